// round 8
// baseline (speedup 1.0000x reference)
#include <cuda_runtime.h>
#include <cuda_bf16.h>
typedef unsigned int u32;
typedef unsigned long long u64;

#define NUM_SEQS 8
#define QLEN 128
#define NQH 32
#define NKVH 8
#define HDIM 128
#define MAXBLOCKS 128
#define NTHR 256
#define SCALE_F 0.08838834764831845f   // 1/sqrt(128)

// ---- smem (bytes): 2 KV buffers (K frags 32KB + V frags 32KB each) + Q frags
#define S_BUF(b) ((b)*65536)
#define KOFF  0
#define VOFF  32768
#define QHOFF 131072
#define QLOFF 163840
#define SMEM_BYTES 196608

__device__ __forceinline__ void bsplit(float x, float y, u32& hi, u32& lo){
    __nv_bfloat162 h = __floats2bfloat162_rn(x, y);
    float hx = __low2float(h), hy = __high2float(h);
    __nv_bfloat162 l = __floats2bfloat162_rn(x - hx, y - hy);
    hi = *reinterpret_cast<u32*>(&h);
    lo = *reinterpret_cast<u32*>(&l);
}

__device__ __forceinline__ void mma16816(float* c, const u32* a, u32 b0, u32 b1){
    asm volatile(
        "mma.sync.aligned.m16n8k16.row.col.f32.bf16.bf16.f32 "
        "{%0,%1,%2,%3},{%4,%5,%6,%7},{%8,%9},{%0,%1,%2,%3};"
        : "+f"(c[0]), "+f"(c[1]), "+f"(c[2]), "+f"(c[3])
        : "r"(a[0]), "r"(a[1]), "r"(a[2]), "r"(a[3]), "r"(b0), "r"(b1));
}

extern __shared__ char smem[];

// K staging: each thread builds ONE fragment line: (l, ks, qq) ->
// d = {16ks+2qq, +1, +8, +9}; dst lane = (l&7)*4+qq, tile nt=l>>3.
__device__ __forceinline__ void stage_k(char* dst, const float* kcache,
                                        const int* btp, int hkv, int tid){
    #pragma unroll
    for (int it = 0; it < 8; it++){
        int l  = tid & 63;
        int f  = it*4 + (tid >> 6);        // 0..31
        int ks = f >> 2, qq = f & 3;
        int pb = btp[l >> 4];
        const float* kb = kcache + ((size_t)pb*NKVH + hkv)*2048 + (l & 15);
        int d0 = ks*16 + 2*qq;
        float x0 = kb[d0*16],     x1 = kb[(d0+1)*16];
        float x2 = kb[(d0+8)*16], x3 = kb[(d0+9)*16];
        u32 b0h,b0l,b1h,b1l; bsplit(x0,x1,b0h,b0l); bsplit(x2,x3,b1h,b1l);
        int nt = l >> 3;
        int fl = ((l&7)*4 + qq) ^ (nt & 3);
        *reinterpret_cast<uint4*>(dst + KOFF + ((nt*8 + ks)*32 + fl)*16)
            = make_uint4(b0h, b1h, b0l, b1l);
    }
}

// V staging: (dv, ksv, qq): l = {16ksv+2qq, +1, +8, +9} (block j = ksv).
__device__ __forceinline__ void stage_v(char* dst, const float* vcache,
                                        const int* btp, int hkv, int tid){
    #pragma unroll
    for (int it = 0; it < 8; it++){
        int dv = tid & 127;
        int f  = it*2 + (tid >> 7);        // 0..15
        int ksv = f >> 2, qq = f & 3;
        int pb = btp[ksv];
        const float* vb = vcache + ((size_t)pb*NKVH + hkv)*2048 + dv*16;
        float2 x01 = *reinterpret_cast<const float2*>(vb + 2*qq);
        float2 x89 = *reinterpret_cast<const float2*>(vb + 2*qq + 8);
        u32 b0h,b0l,b1h,b1l; bsplit(x01.x,x01.y,b0h,b0l); bsplit(x89.x,x89.y,b1h,b1l);
        int ntv = dv >> 3;
        int fl = ((dv&7)*4 + qq) ^ (ntv & 3);
        *reinterpret_cast<uint4*>(dst + VOFF + ((ksv*16 + ntv)*32 + fl)*16)
            = make_uint4(b0h, b1h, b0l, b1l);
    }
}

__global__ void __launch_bounds__(NTHR, 1) Model_3470333575380_kernel(
    const float* __restrict__ query, const float* __restrict__ key_cache,
    const float* __restrict__ value_cache, const int* __restrict__ block_tables,
    const int* __restrict__ seq_lens, float* __restrict__ out)
{
    const int tid  = threadIdx.x;
    const int lane = tid & 31;
    const int w    = tid >> 5;      // warp owns q rows w*16 .. w*16+15
    const int g    = lane >> 2;
    const int qq   = lane & 3;

    const int cta = blockIdx.x;
    const int sp  = cta & 1;                   // segment pair
    const int h   = (cta >> 1) & (NQH - 1);
    const int s   = cta >> 6;
    const int hkv = h >> 2;

    const int seq_len = seq_lens[s];
    const int ctx = seq_len - QLEN;
    const int qa0 = ctx + w*16 + g;            // causal bound row g
    const int qa1 = qa0 + 8;

    // ---- stage Q -> frag-major smem (hi/lo) ----
    {
        const float* q0 = query + ((size_t)(s*QLEN + w*16 + g)*NQH + h)*HDIM;
        const float* q8 = q0 + (size_t)8*NQH*HDIM;
        #pragma unroll
        for (int ks = 0; ks < 8; ks++){
            int d0 = ks*16 + 2*qq;
            float2 x0 = *reinterpret_cast<const float2*>(q0 + d0);
            float2 x1 = *reinterpret_cast<const float2*>(q8 + d0);
            float2 x2 = *reinterpret_cast<const float2*>(q0 + d0 + 8);
            float2 x3 = *reinterpret_cast<const float2*>(q8 + d0 + 8);
            u32 a0h,a0l,a1h,a1l,a2h,a2l,a3h,a3l;
            bsplit(x0.x*SCALE_F, x0.y*SCALE_F, a0h, a0l);
            bsplit(x1.x*SCALE_F, x1.y*SCALE_F, a1h, a1l);
            bsplit(x2.x*SCALE_F, x2.y*SCALE_F, a2h, a2l);
            bsplit(x3.x*SCALE_F, x3.y*SCALE_F, a3h, a3l);
            int off = ((w*8 + ks)*32 + lane)*16;
            *reinterpret_cast<uint4*>(smem + QHOFF + off) = make_uint4(a0h,a1h,a2h,a3h);
            *reinterpret_cast<uint4*>(smem + QLOFF + off) = make_uint4(a0l,a1l,a2l,a3l);
        }
    }

    const int* btbase = block_tables + s*MAXBLOCKS + sp*64;
    stage_k(smem + S_BUF(0), key_cache,   btbase, hkv, tid);
    stage_v(smem + S_BUF(0), value_cache, btbase, hkv, tid);
    __syncthreads();

    float dacc[16][4];
    #pragma unroll
    for (int i = 0; i < 16; i++){ dacc[i][0]=0.f; dacc[i][1]=0.f; dacc[i][2]=0.f; dacc[i][3]=0.f; }
    float m0 = -1e30f, m1 = -1e30f;

    const char* qhp = smem + QHOFF + (w*8*32 + lane)*16;
    const char* qlp = smem + QLOFF + (w*8*32 + lane)*16;

    #pragma unroll 1
    for (int st = 0; st < 16; st++){
        char* bufc = smem + S_BUF(st & 1);
        char* bufn = smem + S_BUF((st & 1) ^ 1);
        const int lb = sp*1024 + st*64;

        // prefetch next stage K (writes other buffer; overlaps with QK below)
        if (st < 15) stage_k(bufn, key_cache, btbase + (st+1)*4, hkv, tid);

        // ---- QK: S[16 x 64] per warp, 3-pass bf16, frag-major LDS ----
        float sacc[8][4];
        #pragma unroll
        for (int i = 0; i < 8; i++){ sacc[i][0]=0.f; sacc[i][1]=0.f; sacc[i][2]=0.f; sacc[i][3]=0.f; }
        #pragma unroll
        for (int ks = 0; ks < 8; ks++){
            uint4 ah4 = *reinterpret_cast<const uint4*>(qhp + ks*512);
            uint4 al4 = *reinterpret_cast<const uint4*>(qlp + ks*512);
            u32 ah[4] = {ah4.x, ah4.y, ah4.z, ah4.w};
            u32 al[4] = {al4.x, al4.y, al4.z, al4.w};
            #pragma unroll
            for (int nt = 0; nt < 8; nt++){
                uint4 kf = *reinterpret_cast<const uint4*>(
                    bufc + KOFF + ((nt*8 + ks)*32 + (lane ^ (nt & 3)))*16);
                mma16816(sacc[nt], ah, kf.x, kf.y);
                mma16816(sacc[nt], al, kf.x, kf.y);
                mma16816(sacc[nt], ah, kf.z, kf.w);
            }
        }

        // prefetch next stage V
        if (st < 15) stage_v(bufn, value_cache, btbase + (st+1)*4, hkv, tid);

        // ---- softcap + causal + p = exp(scv - 30), static max ----
        #pragma unroll
        for (int nt = 0; nt < 8; nt++){
            #pragma unroll
            for (int e = 0; e < 4; e++){
                int lg  = lb + nt*8 + qq*2 + (e & 1);
                int row = (e < 2) ? qa0 : qa1;
                float sv = sacc[nt][e];
                float ex = __expf(sv * (1.0f/15.0f));
                float u  = __fdividef(60.0f, ex + 1.0f);
                float scv = 30.0f - u;
                bool ok = (lg <= row);
                float p = ok ? __expf(-u) : 0.0f;
                if (ok){ if (e < 2) m0 = fmaxf(m0, scv); else m1 = fmaxf(m1, scv); }
                sacc[nt][e] = p;
            }
        }

        // ---- PV: D[16 x 128] += P * V, 3-pass bf16, frag-major LDS ----
        #pragma unroll
        for (int ksv = 0; ksv < 4; ksv++){
            u32 ph[4], pl[4];
            const float* p0 = sacc[2*ksv];
            const float* p1 = sacc[2*ksv + 1];
            bsplit(p0[0], p0[1], ph[0], pl[0]);
            bsplit(p0[2], p0[3], ph[1], pl[1]);
            bsplit(p1[0], p1[1], ph[2], pl[2]);
            bsplit(p1[2], p1[3], ph[3], pl[3]);
            #pragma unroll
            for (int ntv = 0; ntv < 16; ntv++){
                uint4 vf = *reinterpret_cast<const uint4*>(
                    bufc + VOFF + ((ksv*16 + ntv)*32 + (lane ^ (ntv & 3)))*16);
                mma16816(dacc[ntv], ph, vf.x, vf.y);
                mma16816(dacc[ntv], pl, vf.x, vf.y);
                mma16816(dacc[ntv], ph, vf.z, vf.w);
            }
        }

        // ---- segment boundary: scale by exp(30 - m), write, reset ----
        if ((st & 7) == 7){
            float a0 = m0, a1 = m1;
            #pragma unroll
            for (int o = 1; o <= 2; o <<= 1){
                a0 = fmaxf(a0, __shfl_xor_sync(0xffffffffu, a0, o));
                a1 = fmaxf(a1, __shfl_xor_sync(0xffffffffu, a1, o));
            }
            float sc0 = (a0 > -100.0f) ? __expf(30.0f - a0) : 0.0f;
            float sc1 = (a1 > -100.0f) ? __expf(30.0f - a1) : 0.0f;
            const int seg = sp*2 + (st >> 3);
            const int t0 = s*QLEN + w*16 + g;
            float* o0 = out + (((size_t)t0*NQH + h)*4 + seg)*HDIM;
            float* o1 = o0 + (size_t)8*NQH*4*HDIM;
            #pragma unroll
            for (int nt = 0; nt < 16; nt++){
                int dv = nt*8 + qq*2;
                *reinterpret_cast<float2*>(o0 + dv) =
                    make_float2(dacc[nt][0]*sc0, dacc[nt][1]*sc0);
                *reinterpret_cast<float2*>(o1 + dv) =
                    make_float2(dacc[nt][2]*sc1, dacc[nt][3]*sc1);
                dacc[nt][0]=0.f; dacc[nt][1]=0.f; dacc[nt][2]=0.f; dacc[nt][3]=0.f;
            }
            m0 = -1e30f; m1 = -1e30f;
        }
        __syncthreads();
    }
}

extern "C" void kernel_launch(void* const* d_in, const int* in_sizes, int n_in,
                              void* d_out, int out_size) {
    (void)in_sizes; (void)n_in; (void)out_size;
    const float* query        = (const float*)d_in[0];
    const float* key_cache    = (const float*)d_in[1];
    const float* value_cache  = (const float*)d_in[2];
    const int*   block_tables = (const int*)d_in[3];
    const int*   seq_lens     = (const int*)d_in[4];
    float* out = (float*)d_out;

    cudaFuncSetAttribute(Model_3470333575380_kernel,
                         cudaFuncAttributeMaxDynamicSharedMemorySize, SMEM_BYTES);
    Model_3470333575380_kernel<<<NUM_SEQS*NQH*2, NTHR, SMEM_BYTES>>>(
        query, key_cache, value_cache, block_tables, seq_lens, out);
}

// round 9
// speedup vs baseline: 1.2380x; 1.2380x over previous
#include <cuda_runtime.h>
#include <cuda_bf16.h>
typedef unsigned int u32;
typedef unsigned long long u64;

#define NUM_SEQS 8
#define QLEN 128
#define NQH 32
#define NKVH 8
#define HDIM 128
#define MAXBLOCKS 128
#define NTHR 256
#define SCALE_F 0.08838834764831845f   // 1/sqrt(128)

// 8 KB fragment chunk per (physical block, kv head), K and V separately.
// K chunk: [ntl<2][ks<8][lane<32] x 16B   (b0h,b1h,b0l,b1l)
// V chunk: [ntv<16][lane<32]      x 16B
__device__ __align__(16) unsigned char g_kfrag[(size_t)8192 * 8192];  // 64 MB
__device__ __align__(16) unsigned char g_vfrag[(size_t)8192 * 8192];  // 64 MB

// ---- smem: two 64KB staging buffers (K 32KB + V 32KB each) ----
#define KOFF 0
#define VOFF 32768
#define SBUF 65536
#define SMEM_BYTES 131072

__device__ __forceinline__ void bsplit(float x, float y, u32& hi, u32& lo){
    __nv_bfloat162 h = __floats2bfloat162_rn(x, y);
    float hx = __low2float(h), hy = __high2float(h);
    __nv_bfloat162 l = __floats2bfloat162_rn(x - hx, y - hy);
    hi = *reinterpret_cast<u32*>(&h);
    lo = *reinterpret_cast<u32*>(&l);
}
__device__ __forceinline__ void mma16816(float* c, const u32* a, u32 b0, u32 b1){
    asm volatile(
        "mma.sync.aligned.m16n8k16.row.col.f32.bf16.bf16.f32 "
        "{%0,%1,%2,%3},{%4,%5,%6,%7},{%8,%9},{%0,%1,%2,%3};"
        : "+f"(c[0]), "+f"(c[1]), "+f"(c[2]), "+f"(c[3])
        : "r"(a[0]), "r"(a[1]), "r"(a[2]), "r"(a[3]), "r"(b0), "r"(b1));
}
__device__ __forceinline__ u32 smem_u32(const void* p){
    u32 a; asm("{ .reg .u64 t; cvta.to.shared.u64 t, %1; cvt.u32.u64 %0, t; }":"=r"(a):"l"(p));
    return a;
}
#define CPA16(d, s) asm volatile("cp.async.cg.shared.global [%0], [%1], 16;"::"r"(d),"l"(s))
#define CPA_COMMIT() asm volatile("cp.async.commit_group;" ::: "memory")
#define CPA_WAIT(n)  asm volatile("cp.async.wait_group %0;" :: "n"(n) : "memory")

// =============== pre-pass: fp32 paged KV -> bf16 hi/lo fragment chunks ======
__global__ void __launch_bounds__(256, 4) convert_kv_kernel(
    const float* __restrict__ kc, const float* __restrict__ vc)
{
    const int b = blockIdx.x;              // b = pb*8 + hkv
    const int tid = threadIdx.x;
    const float* kb = kc + (size_t)b * 2048;
    const float* vb = vc + (size_t)b * 2048;
    unsigned char* kd = g_kfrag + ((size_t)b << 13);
    unsigned char* vd = g_vfrag + ((size_t)b << 13);

    // K: 512 items = (lb<16, ks<8, qq<4)
    #pragma unroll
    for (int it = 0; it < 2; it++){
        int lb = tid & 15;
        int f  = it*16 + (tid >> 4);       // 0..31
        int ks = f >> 2, qq = f & 3;
        int d0 = ks*16 + 2*qq;
        float x0 = kb[(d0+0)*16 + lb], x1 = kb[(d0+1)*16 + lb];
        float x2 = kb[(d0+8)*16 + lb], x3 = kb[(d0+9)*16 + lb];
        u32 b0h,b0l,b1h,b1l; bsplit(x0,x1,b0h,b0l); bsplit(x2,x3,b1h,b1l);
        int ntl = lb >> 3, fl = (lb&7)*4 + qq;
        *reinterpret_cast<uint4*>(kd + ((ntl*8 + ks)*32 + fl)*16)
            = make_uint4(b0h, b1h, b0l, b1l);
    }
    // V: 512 items = (dv<128, qq<4)
    #pragma unroll
    for (int it = 0; it < 2; it++){
        int idx = it*256 + tid;            // 0..511
        int dv = idx >> 2, qq = idx & 3;
        const float* vr = vb + dv*16;
        float2 x01 = *reinterpret_cast<const float2*>(vr + 2*qq);
        float2 x89 = *reinterpret_cast<const float2*>(vr + 2*qq + 8);
        u32 b0h,b0l,b1h,b1l; bsplit(x01.x,x01.y,b0h,b0l); bsplit(x89.x,x89.y,b1h,b1l);
        int ntv = dv >> 3, fl = (dv&7)*4 + qq;
        *reinterpret_cast<uint4*>(vd + (ntv*32 + fl)*16)
            = make_uint4(b0h, b1h, b0l, b1l);
    }
}

// =============== main attention kernel ======================================
extern __shared__ char smem[];

__device__ __forceinline__ void issue_stage(u32 smb, const int* btp, int hkv, int tid){
    size_t kc0 = ((size_t)(btp[0]*8 + hkv)) << 13;
    size_t kc1 = ((size_t)(btp[1]*8 + hkv)) << 13;
    size_t kc2 = ((size_t)(btp[2]*8 + hkv)) << 13;
    size_t kc3 = ((size_t)(btp[3]*8 + hkv)) << 13;
    size_t srcs[4] = {kc0, kc1, kc2, kc3};
    #pragma unroll
    for (int it = 0; it < 8; it++){
        int idx = it*NTHR + tid;           // 0..2047
        int j = idx >> 9, off = (idx & 511) * 16;
        CPA16(smb + KOFF + j*8192 + off, g_kfrag + srcs[j] + off);
    }
    #pragma unroll
    for (int it = 0; it < 8; it++){
        int idx = it*NTHR + tid;
        int j = idx >> 9, off = (idx & 511) * 16;
        CPA16(smb + VOFF + j*8192 + off, g_vfrag + srcs[j] + off);
    }
}

__global__ void __launch_bounds__(NTHR, 1) Model_3470333575380_kernel(
    const float* __restrict__ query, const int* __restrict__ block_tables,
    const int* __restrict__ seq_lens, float* __restrict__ out)
{
    const int tid  = threadIdx.x;
    const int lane = tid & 31;
    const int w    = tid >> 5;       // warp owns q rows w*16 .. w*16+15
    const int g    = lane >> 2;
    const int qq   = lane & 3;

    const int cta = blockIdx.x;
    const int sp  = cta & 1;
    const int h   = (cta >> 1) & (NQH - 1);
    const int s   = cta >> 6;
    const int hkv = h >> 2;

    const int seq_len = seq_lens[s];
    const int ctx = seq_len - QLEN;
    const int qa0 = ctx + w*16 + g;
    const int qa1 = qa0 + 8;

    const u32 smb = smem_u32(smem);
    const int* btbase = block_tables + s*MAXBLOCKS + sp*64;

    // prologue: prefetch stages 0 and 1
    issue_stage(smb,        btbase,     hkv, tid); CPA_COMMIT();
    issue_stage(smb + SBUF, btbase + 4, hkv, tid); CPA_COMMIT();

    // ---- Q fragments (hi/lo) in registers (overlaps with cp.async) ----
    u32 qh[8][4], ql[8][4];
    {
        const float* q0 = query + ((size_t)(s*QLEN + w*16 + g)*NQH + h)*HDIM;
        const float* q8 = q0 + (size_t)8*NQH*HDIM;
        #pragma unroll
        for (int ks = 0; ks < 8; ks++){
            int d0 = ks*16 + 2*qq;
            float2 x0 = *reinterpret_cast<const float2*>(q0 + d0);
            float2 x1 = *reinterpret_cast<const float2*>(q8 + d0);
            float2 x2 = *reinterpret_cast<const float2*>(q0 + d0 + 8);
            float2 x3 = *reinterpret_cast<const float2*>(q8 + d0 + 8);
            bsplit(x0.x*SCALE_F, x0.y*SCALE_F, qh[ks][0], ql[ks][0]);
            bsplit(x1.x*SCALE_F, x1.y*SCALE_F, qh[ks][1], ql[ks][1]);
            bsplit(x2.x*SCALE_F, x2.y*SCALE_F, qh[ks][2], ql[ks][2]);
            bsplit(x3.x*SCALE_F, x3.y*SCALE_F, qh[ks][3], ql[ks][3]);
        }
    }

    float dacc[16][4];
    #pragma unroll
    for (int i = 0; i < 16; i++){ dacc[i][0]=0.f; dacc[i][1]=0.f; dacc[i][2]=0.f; dacc[i][3]=0.f; }
    float m0 = -1e30f, m1 = -1e30f;

    CPA_WAIT(1);
    __syncthreads();

    #pragma unroll 1
    for (int st = 0; st < 16; st++){
        const char* bufc = smem + (st & 1)*SBUF;
        const int lb = sp*1024 + st*64;

        // ---- QK: S[16 x 64] per warp, 3-pass bf16, 1 LDS.128 per tile ----
        float sacc[8][4];
        #pragma unroll
        for (int i = 0; i < 8; i++){ sacc[i][0]=0.f; sacc[i][1]=0.f; sacc[i][2]=0.f; sacc[i][3]=0.f; }
        #pragma unroll
        for (int ks = 0; ks < 8; ks++){
            #pragma unroll
            for (int nt = 0; nt < 8; nt++){
                uint4 kf = *reinterpret_cast<const uint4*>(
                    bufc + KOFF + ((nt*8 + ks)*32 + lane)*16);
                mma16816(sacc[nt], qh[ks], kf.x, kf.y);
                mma16816(sacc[nt], ql[ks], kf.x, kf.y);
                mma16816(sacc[nt], qh[ks], kf.z, kf.w);
            }
        }

        // ---- softcap + causal + p = exp(scv - 30), static max ----
        #pragma unroll
        for (int nt = 0; nt < 8; nt++){
            #pragma unroll
            for (int e = 0; e < 4; e++){
                int lg  = lb + nt*8 + qq*2 + (e & 1);
                int row = (e < 2) ? qa0 : qa1;
                float sv = sacc[nt][e];
                float ex = __expf(sv * (1.0f/15.0f));
                float u  = __fdividef(60.0f, ex + 1.0f);
                float scv = 30.0f - u;
                bool ok = (lg <= row);
                float p = ok ? __expf(-u) : 0.0f;
                if (ok){ if (e < 2) m0 = fmaxf(m0, scv); else m1 = fmaxf(m1, scv); }
                sacc[nt][e] = p;
            }
        }

        // ---- PV: D[16 x 128] += P * V, 3-pass bf16 ----
        #pragma unroll
        for (int ksv = 0; ksv < 4; ksv++){
            u32 ph[4], pl[4];
            const float* p0 = sacc[2*ksv];
            const float* p1 = sacc[2*ksv + 1];
            bsplit(p0[0], p0[1], ph[0], pl[0]);
            bsplit(p0[2], p0[3], ph[1], pl[1]);
            bsplit(p1[0], p1[1], ph[2], pl[2]);
            bsplit(p1[2], p1[3], ph[3], pl[3]);
            #pragma unroll
            for (int ntv = 0; ntv < 16; ntv++){
                uint4 vf = *reinterpret_cast<const uint4*>(
                    bufc + VOFF + ((ksv*16 + ntv)*32 + lane)*16);
                mma16816(dacc[ntv], ph, vf.x, vf.y);
                mma16816(dacc[ntv], pl, vf.x, vf.y);
                mma16816(dacc[ntv], ph, vf.z, vf.w);
            }
        }

        // ---- segment boundary: scale by exp(30 - m), write, reset ----
        if ((st & 7) == 7){
            float a0 = m0, a1 = m1;
            #pragma unroll
            for (int o = 1; o <= 2; o <<= 1){
                a0 = fmaxf(a0, __shfl_xor_sync(0xffffffffu, a0, o));
                a1 = fmaxf(a1, __shfl_xor_sync(0xffffffffu, a1, o));
            }
            float sc0 = (a0 > -100.0f) ? __expf(30.0f - a0) : 0.0f;
            float sc1 = (a1 > -100.0f) ? __expf(30.0f - a1) : 0.0f;
            const int seg = sp*2 + (st >> 3);
            const int t0 = s*QLEN + w*16 + g;
            float* o0 = out + (((size_t)t0*NQH + h)*4 + seg)*HDIM;
            float* o1 = o0 + (size_t)8*NQH*4*HDIM;
            #pragma unroll
            for (int nt = 0; nt < 16; nt++){
                int dv = nt*8 + qq*2;
                *reinterpret_cast<float2*>(o0 + dv) =
                    make_float2(dacc[nt][0]*sc0, dacc[nt][1]*sc0);
                *reinterpret_cast<float2*>(o1 + dv) =
                    make_float2(dacc[nt][2]*sc1, dacc[nt][3]*sc1);
                dacc[nt][0]=0.f; dacc[nt][1]=0.f; dacc[nt][2]=0.f; dacc[nt][3]=0.f;
            }
            m0 = -1e30f; m1 = -1e30f;
        }

        __syncthreads();                    // all warps done reading bufc
        if (st + 2 < 16){
            issue_stage(smb + (st & 1)*SBUF, btbase + (st+2)*4, hkv, tid);
            CPA_COMMIT();
            CPA_WAIT(1);                    // stage st+1 buffer complete
        } else {
            CPA_WAIT(0);
        }
        __syncthreads();
    }
}

extern "C" void kernel_launch(void* const* d_in, const int* in_sizes, int n_in,
                              void* d_out, int out_size) {
    (void)in_sizes; (void)n_in; (void)out_size;
    const float* query        = (const float*)d_in[0];
    const float* key_cache    = (const float*)d_in[1];
    const float* value_cache  = (const float*)d_in[2];
    const int*   block_tables = (const int*)d_in[3];
    const int*   seq_lens     = (const int*)d_in[4];
    float* out = (float*)d_out;

    convert_kv_kernel<<<8192, 256>>>(key_cache, value_cache);

    cudaFuncSetAttribute(Model_3470333575380_kernel,
                         cudaFuncAttributeMaxDynamicSharedMemorySize, SMEM_BYTES);
    Model_3470333575380_kernel<<<NUM_SEQS*NQH*2, NTHR, SMEM_BYTES>>>(
        query, block_tables, seq_lens, out);
}

// round 10
// speedup vs baseline: 1.4810x; 1.1963x over previous
#include <cuda_runtime.h>
#include <cuda_bf16.h>
typedef unsigned int u32;
typedef unsigned long long u64;

#define NUM_SEQS 8
#define QLEN 128
#define NQH 32
#define NKVH 8
#define HDIM 128
#define MAXBLOCKS 128
#define NTHR 128
#define SCALE_F 0.08838834764831845f   // 1/sqrt(128)

// 8 KB fragment chunk per (physical block, kv head), K and V separately.
// K chunk: [ntl<2][ks<8][lane<32] x 16B   (b0h,b1h,b0l,b1l)
// V chunk: [ntv<16][lane<32]      x 16B
__device__ __align__(16) unsigned char g_kfrag[(size_t)8192 * 8192];  // 64 MB
__device__ __align__(16) unsigned char g_vfrag[(size_t)8192 * 8192];  // 64 MB

// ---- smem: two 32KB staging buffers (K 16KB + V 16KB each) ----
#define KOFF 0
#define VOFF 16384
#define SBUF 32768
#define SMEM_BYTES 65536

__device__ __forceinline__ void bsplit(float x, float y, u32& hi, u32& lo){
    __nv_bfloat162 h = __floats2bfloat162_rn(x, y);
    float hx = __low2float(h), hy = __high2float(h);
    __nv_bfloat162 l = __floats2bfloat162_rn(x - hx, y - hy);
    hi = *reinterpret_cast<u32*>(&h);
    lo = *reinterpret_cast<u32*>(&l);
}
__device__ __forceinline__ void mma16816(float* c, const u32* a, u32 b0, u32 b1){
    asm volatile(
        "mma.sync.aligned.m16n8k16.row.col.f32.bf16.bf16.f32 "
        "{%0,%1,%2,%3},{%4,%5,%6,%7},{%8,%9},{%0,%1,%2,%3};"
        : "+f"(c[0]), "+f"(c[1]), "+f"(c[2]), "+f"(c[3])
        : "r"(a[0]), "r"(a[1]), "r"(a[2]), "r"(a[3]), "r"(b0), "r"(b1));
}
__device__ __forceinline__ u32 smem_u32(const void* p){
    u32 a; asm("{ .reg .u64 t; cvta.to.shared.u64 t, %1; cvt.u32.u64 %0, t; }":"=r"(a):"l"(p));
    return a;
}
#define CPA16(d, s) asm volatile("cp.async.cg.shared.global [%0], [%1], 16;"::"r"(d),"l"(s))
#define CPA_COMMIT() asm volatile("cp.async.commit_group;" ::: "memory")
#define CPA_WAIT(n)  asm volatile("cp.async.wait_group %0;" :: "n"(n) : "memory")

// =============== pre-pass: fp32 paged KV -> bf16 hi/lo fragment chunks ======
__global__ void __launch_bounds__(256, 4) convert_kv_kernel(
    const float* __restrict__ kc, const float* __restrict__ vc)
{
    const int b = blockIdx.x;              // b = pb*8 + hkv
    const int tid = threadIdx.x;
    const float* kb = kc + (size_t)b * 2048;
    const float* vb = vc + (size_t)b * 2048;
    unsigned char* kd = g_kfrag + ((size_t)b << 13);
    unsigned char* vd = g_vfrag + ((size_t)b << 13);

    #pragma unroll
    for (int it = 0; it < 2; it++){
        int lb = tid & 15;
        int f  = it*16 + (tid >> 4);       // 0..31
        int ks = f >> 2, qq = f & 3;
        int d0 = ks*16 + 2*qq;
        float x0 = kb[(d0+0)*16 + lb], x1 = kb[(d0+1)*16 + lb];
        float x2 = kb[(d0+8)*16 + lb], x3 = kb[(d0+9)*16 + lb];
        u32 b0h,b0l,b1h,b1l; bsplit(x0,x1,b0h,b0l); bsplit(x2,x3,b1h,b1l);
        int ntl = lb >> 3, fl = (lb&7)*4 + qq;
        *reinterpret_cast<uint4*>(kd + ((ntl*8 + ks)*32 + fl)*16)
            = make_uint4(b0h, b1h, b0l, b1l);
    }
    #pragma unroll
    for (int it = 0; it < 2; it++){
        int idx = it*256 + tid;            // 0..511
        int dv = idx >> 2, qq = idx & 3;
        const float* vr = vb + dv*16;
        float2 x01 = *reinterpret_cast<const float2*>(vr + 2*qq);
        float2 x89 = *reinterpret_cast<const float2*>(vr + 2*qq + 8);
        u32 b0h,b0l,b1h,b1l; bsplit(x01.x,x01.y,b0h,b0l); bsplit(x89.x,x89.y,b1h,b1l);
        int ntv = dv >> 3, fl = (dv&7)*4 + qq;
        *reinterpret_cast<uint4*>(vd + (ntv*32 + fl)*16)
            = make_uint4(b0h, b1h, b0l, b1l);
    }
}

// =============== main attention kernel ======================================
extern __shared__ char smem[];

// stage = 2 paged blocks (32 keys): copy 2x 8KB K + 2x 8KB V chunks.
__device__ __forceinline__ void issue_stage(u32 smb, const int* btp, int hkv, int tid){
    size_t c0 = ((size_t)(btp[0]*8 + hkv)) << 13;
    size_t c1 = ((size_t)(btp[1]*8 + hkv)) << 13;
    size_t srcs[2] = {c0, c1};
    #pragma unroll
    for (int it = 0; it < 8; it++){
        int idx = it*NTHR + tid;           // 0..1023
        int j = idx >> 9, off = (idx & 511) * 16;
        CPA16(smb + KOFF + j*8192 + off, g_kfrag + srcs[j] + off);
    }
    #pragma unroll
    for (int it = 0; it < 8; it++){
        int idx = it*NTHR + tid;
        int j = idx >> 9, off = (idx & 511) * 16;
        CPA16(smb + VOFF + j*8192 + off, g_vfrag + srcs[j] + off);
    }
}

__global__ void __launch_bounds__(NTHR, 2) Model_3470333575380_kernel(
    const float* __restrict__ query, const int* __restrict__ block_tables,
    const int* __restrict__ seq_lens, float* __restrict__ out)
{
    const int tid  = threadIdx.x;
    const int lane = tid & 31;
    const int w    = tid >> 5;       // 4 warps; warp owns q rows w*16..w*16+15
    const int g    = lane >> 2;
    const int qq   = lane & 3;

    const int cta = blockIdx.x;
    const int sp  = cta & 1;                    // segment pair
    const int qt  = (cta >> 1) & 1;             // q half (64 rows)
    const int h   = (cta >> 2) & (NQH - 1);
    const int s   = cta >> 7;
    const int hkv = h >> 2;

    const int seq_len = seq_lens[s];
    const int ctx = seq_len - QLEN;
    const int qa0 = ctx + qt*64 + w*16 + g;
    const int qa1 = qa0 + 8;

    const u32 smb = smem_u32(smem);
    const int* btbase = block_tables + s*MAXBLOCKS + sp*64;

    // prologue: prefetch stages 0 and 1
    issue_stage(smb,        btbase,     hkv, tid); CPA_COMMIT();
    issue_stage(smb + SBUF, btbase + 2, hkv, tid); CPA_COMMIT();

    // ---- Q fragments (hi/lo) in registers ----
    u32 qh[8][4], ql[8][4];
    {
        const float* q0 = query + ((size_t)(s*QLEN + qt*64 + w*16 + g)*NQH + h)*HDIM;
        const float* q8 = q0 + (size_t)8*NQH*HDIM;
        #pragma unroll
        for (int ks = 0; ks < 8; ks++){
            int d0 = ks*16 + 2*qq;
            float2 x0 = *reinterpret_cast<const float2*>(q0 + d0);
            float2 x1 = *reinterpret_cast<const float2*>(q8 + d0);
            float2 x2 = *reinterpret_cast<const float2*>(q0 + d0 + 8);
            float2 x3 = *reinterpret_cast<const float2*>(q8 + d0 + 8);
            bsplit(x0.x*SCALE_F, x0.y*SCALE_F, qh[ks][0], ql[ks][0]);
            bsplit(x1.x*SCALE_F, x1.y*SCALE_F, qh[ks][1], ql[ks][1]);
            bsplit(x2.x*SCALE_F, x2.y*SCALE_F, qh[ks][2], ql[ks][2]);
            bsplit(x3.x*SCALE_F, x3.y*SCALE_F, qh[ks][3], ql[ks][3]);
        }
    }

    float dacc[16][4];
    #pragma unroll
    for (int i = 0; i < 16; i++){ dacc[i][0]=0.f; dacc[i][1]=0.f; dacc[i][2]=0.f; dacc[i][3]=0.f; }
    float m0 = -1e30f, m1 = -1e30f;

    CPA_WAIT(1);
    __syncthreads();

    #pragma unroll 1
    for (int st = 0; st < 32; st++){            // 32 stages x 32 keys
        const char* bufc = smem + (st & 1)*SBUF;
        const int lb = sp*1024 + st*32;

        // ---- QK: S[16 x 32] per warp, 3-pass bf16, 1 LDS.128 per tile ----
        float sacc[4][4];
        #pragma unroll
        for (int i = 0; i < 4; i++){ sacc[i][0]=0.f; sacc[i][1]=0.f; sacc[i][2]=0.f; sacc[i][3]=0.f; }
        #pragma unroll
        for (int ks = 0; ks < 8; ks++){
            #pragma unroll
            for (int nt = 0; nt < 4; nt++){     // nt = j*2 + ntl
                uint4 kf = *reinterpret_cast<const uint4*>(
                    bufc + KOFF + (nt >> 1)*8192 + (((nt & 1)*8 + ks)*32 + lane)*16);
                mma16816(sacc[nt], qh[ks], kf.x, kf.y);
                mma16816(sacc[nt], ql[ks], kf.x, kf.y);
                mma16816(sacc[nt], qh[ks], kf.z, kf.w);
            }
        }

        // ---- softcap + causal + p = exp(scv - 30), static max ----
        #pragma unroll
        for (int nt = 0; nt < 4; nt++){
            #pragma unroll
            for (int e = 0; e < 4; e++){
                int lg  = lb + nt*8 + qq*2 + (e & 1);
                int row = (e < 2) ? qa0 : qa1;
                float sv = sacc[nt][e];
                float ex = __expf(sv * (1.0f/15.0f));
                float u  = __fdividef(60.0f, ex + 1.0f);
                float scv = 30.0f - u;
                bool ok = (lg <= row);
                float p = ok ? __expf(-u) : 0.0f;
                if (ok){ if (e < 2) m0 = fmaxf(m0, scv); else m1 = fmaxf(m1, scv); }
                sacc[nt][e] = p;
            }
        }

        // ---- PV: D[16 x 128] += P * V, 3-pass bf16 ----
        #pragma unroll
        for (int ksv = 0; ksv < 2; ksv++){      // ksv = paged block j
            u32 ph[4], pl[4];
            const float* p0 = sacc[2*ksv];
            const float* p1 = sacc[2*ksv + 1];
            bsplit(p0[0], p0[1], ph[0], pl[0]);
            bsplit(p0[2], p0[3], ph[1], pl[1]);
            bsplit(p1[0], p1[1], ph[2], pl[2]);
            bsplit(p1[2], p1[3], ph[3], pl[3]);
            #pragma unroll
            for (int ntv = 0; ntv < 16; ntv++){
                uint4 vf = *reinterpret_cast<const uint4*>(
                    bufc + VOFF + ksv*8192 + (ntv*32 + lane)*16);
                mma16816(dacc[ntv], ph, vf.x, vf.y);
                mma16816(dacc[ntv], pl, vf.x, vf.y);
                mma16816(dacc[ntv], ph, vf.z, vf.w);
            }
        }

        // ---- segment boundary: scale by exp(30 - m), write, reset ----
        if ((st & 15) == 15){
            float a0 = m0, a1 = m1;
            #pragma unroll
            for (int o = 1; o <= 2; o <<= 1){
                a0 = fmaxf(a0, __shfl_xor_sync(0xffffffffu, a0, o));
                a1 = fmaxf(a1, __shfl_xor_sync(0xffffffffu, a1, o));
            }
            float sc0 = (a0 > -100.0f) ? __expf(30.0f - a0) : 0.0f;
            float sc1 = (a1 > -100.0f) ? __expf(30.0f - a1) : 0.0f;
            const int seg = sp*2 + (st >> 4);
            const int t0 = s*QLEN + qt*64 + w*16 + g;
            float* o0 = out + (((size_t)t0*NQH + h)*4 + seg)*HDIM;
            float* o1 = o0 + (size_t)8*NQH*4*HDIM;
            #pragma unroll
            for (int nt = 0; nt < 16; nt++){
                int dv = nt*8 + qq*2;
                *reinterpret_cast<float2*>(o0 + dv) =
                    make_float2(dacc[nt][0]*sc0, dacc[nt][1]*sc0);
                *reinterpret_cast<float2*>(o1 + dv) =
                    make_float2(dacc[nt][2]*sc1, dacc[nt][3]*sc1);
                dacc[nt][0]=0.f; dacc[nt][1]=0.f; dacc[nt][2]=0.f; dacc[nt][3]=0.f;
            }
            m0 = -1e30f; m1 = -1e30f;
        }

        __syncthreads();                    // all warps done reading bufc
        if (st + 2 < 32){
            issue_stage(smb + (st & 1)*SBUF, btbase + (st+2)*2, hkv, tid);
            CPA_COMMIT();
            CPA_WAIT(1);
        } else {
            CPA_WAIT(0);
        }
        __syncthreads();
    }
}

extern "C" void kernel_launch(void* const* d_in, const int* in_sizes, int n_in,
                              void* d_out, int out_size) {
    (void)in_sizes; (void)n_in; (void)out_size;
    const float* query        = (const float*)d_in[0];
    const float* key_cache    = (const float*)d_in[1];
    const float* value_cache  = (const float*)d_in[2];
    const int*   block_tables = (const int*)d_in[3];
    const int*   seq_lens     = (const int*)d_in[4];
    float* out = (float*)d_out;

    convert_kv_kernel<<<8192, 256>>>(key_cache, value_cache);

    cudaFuncSetAttribute(Model_3470333575380_kernel,
                         cudaFuncAttributeMaxDynamicSharedMemorySize, SMEM_BYTES);
    Model_3470333575380_kernel<<<NUM_SEQS*NQH*2*2, NTHR, SMEM_BYTES>>>(
        query, block_tables, seq_lens, out);
}

// round 12
// speedup vs baseline: 1.5225x; 1.0280x over previous
#include <cuda_runtime.h>
#include <cuda_bf16.h>
typedef unsigned int u32;
typedef unsigned long long u64;

#define NUM_SEQS 8
#define QLEN 128
#define NQH 32
#define NKVH 8
#define HDIM 128
#define MAXBLOCKS 128
#define NTHR 128
#define SCALE_F 0.08838834764831845f   // 1/sqrt(128)

// 8 KB fragment chunk per (physical block, kv head), K and V separately.
// K chunk: [ntl<2][ks<8][lane<32] x 16B   (b0h,b1h,b0l,b1l)
// V chunk: [ntv<16][lane<32]      x 16B
__device__ __align__(16) unsigned char g_kfrag[(size_t)8192 * 8192];  // 64 MB
__device__ __align__(16) unsigned char g_vfrag[(size_t)8192 * 8192];  // 64 MB

// ---- smem: three 32KB staging buffers (K 16KB + V 16KB each) ----
#define KOFF 0
#define VOFF 16384
#define SBUF 32768
#define SMEM_BYTES 98304

// odd Taylor coeffs of 30*tanh(s/30) as poly in u=s^2:  scv = s*P(u)
#define TA0  1.0f
#define TA1 -3.7037037e-4f
#define TA2  1.6460905e-7f
#define TA3 -7.4015300e-11f
#define TA4  3.3330500e-14f
#define TA5 -1.5009900e-17f
#define TA6  6.7599000e-21f

__device__ __forceinline__ void bsplit(float x, float y, u32& hi, u32& lo){
    __nv_bfloat162 h = __floats2bfloat162_rn(x, y);
    float hx = __low2float(h), hy = __high2float(h);
    __nv_bfloat162 l = __floats2bfloat162_rn(x - hx, y - hy);
    hi = *reinterpret_cast<u32*>(&h);
    lo = *reinterpret_cast<u32*>(&l);
}
__device__ __forceinline__ void mma16816(float* c, const u32* a, u32 b0, u32 b1){
    asm volatile(
        "mma.sync.aligned.m16n8k16.row.col.f32.bf16.bf16.f32 "
        "{%0,%1,%2,%3},{%4,%5,%6,%7},{%8,%9},{%0,%1,%2,%3};"
        : "+f"(c[0]), "+f"(c[1]), "+f"(c[2]), "+f"(c[3])
        : "r"(a[0]), "r"(a[1]), "r"(a[2]), "r"(a[3]), "r"(b0), "r"(b1));
}
__device__ __forceinline__ u32 smem_u32(const void* p){
    u32 a; asm("{ .reg .u64 t; cvta.to.shared.u64 t, %1; cvt.u32.u64 %0, t; }":"=r"(a):"l"(p));
    return a;
}
#define CPA16(d, s) asm volatile("cp.async.cg.shared.global [%0], [%1], 16;"::"r"(d),"l"(s))
#define CPA_COMMIT() asm volatile("cp.async.commit_group;" ::: "memory")
#define CPA_WAIT(n)  asm volatile("cp.async.wait_group %0;" :: "n"(n) : "memory")

// =============== pre-pass: fp32 paged KV -> bf16 hi/lo fragment chunks ======
__global__ void __launch_bounds__(256, 4) convert_kv_kernel(
    const float* __restrict__ kc, const float* __restrict__ vc)
{
    const int b = blockIdx.x;              // b = pb*8 + hkv
    const int tid = threadIdx.x;
    const float* kb = kc + (size_t)b * 2048;
    const float* vb = vc + (size_t)b * 2048;
    unsigned char* kd = g_kfrag + ((size_t)b << 13);
    unsigned char* vd = g_vfrag + ((size_t)b << 13);

    #pragma unroll
    for (int it = 0; it < 2; it++){
        int lb = tid & 15;
        int f  = it*16 + (tid >> 4);       // 0..31
        int ks = f >> 2, qq = f & 3;
        int d0 = ks*16 + 2*qq;
        float x0 = kb[(d0+0)*16 + lb], x1 = kb[(d0+1)*16 + lb];
        float x2 = kb[(d0+8)*16 + lb], x3 = kb[(d0+9)*16 + lb];
        u32 b0h,b0l,b1h,b1l; bsplit(x0,x1,b0h,b0l); bsplit(x2,x3,b1h,b1l);
        int ntl = lb >> 3, fl = (lb&7)*4 + qq;
        *reinterpret_cast<uint4*>(kd + ((ntl*8 + ks)*32 + fl)*16)
            = make_uint4(b0h, b1h, b0l, b1l);
    }
    #pragma unroll
    for (int it = 0; it < 2; it++){
        int idx = it*256 + tid;            // 0..511
        int dv = idx >> 2, qq = idx & 3;
        const float* vr = vb + dv*16;
        float2 x01 = *reinterpret_cast<const float2*>(vr + 2*qq);
        float2 x89 = *reinterpret_cast<const float2*>(vr + 2*qq + 8);
        u32 b0h,b0l,b1h,b1l; bsplit(x01.x,x01.y,b0h,b0l); bsplit(x89.x,x89.y,b1h,b1l);
        int ntv = dv >> 3, fl = (dv&7)*4 + qq;
        *reinterpret_cast<uint4*>(vd + (ntv*32 + fl)*16)
            = make_uint4(b0h, b1h, b0l, b1l);
    }
}

// =============== main attention kernel ======================================
extern __shared__ char smem[];

// stage = 2 paged blocks (32 keys): copy 2x 8KB K + 2x 8KB V chunks.
__device__ __forceinline__ void issue_stage(u32 smb, const int* btp, int hkv, int tid){
    size_t c0 = ((size_t)(btp[0]*8 + hkv)) << 13;
    size_t c1 = ((size_t)(btp[1]*8 + hkv)) << 13;
    size_t srcs[2] = {c0, c1};
    #pragma unroll
    for (int it = 0; it < 8; it++){
        int idx = it*NTHR + tid;           // 0..1023
        int j = idx >> 9, off = (idx & 511) * 16;
        CPA16(smb + KOFF + j*8192 + off, g_kfrag + srcs[j] + off);
    }
    #pragma unroll
    for (int it = 0; it < 8; it++){
        int idx = it*NTHR + tid;
        int j = idx >> 9, off = (idx & 511) * 16;
        CPA16(smb + VOFF + j*8192 + off, g_vfrag + srcs[j] + off);
    }
}

__global__ void __launch_bounds__(NTHR, 2) Model_3470333575380_kernel(
    const float* __restrict__ query, const int* __restrict__ block_tables,
    const int* __restrict__ seq_lens, float* __restrict__ out)
{
    const int tid  = threadIdx.x;
    const int lane = tid & 31;
    const int w    = tid >> 5;       // 4 warps; warp owns q rows w*16..w*16+15
    const int g    = lane >> 2;
    const int qq   = lane & 3;

    const int cta = blockIdx.x;
    const int sp  = cta & 1;                    // segment pair
    const int qt  = (cta >> 1) & 1;             // q half (64 rows)
    const int h   = (cta >> 2) & (NQH - 1);
    const int s   = cta >> 7;
    const int hkv = h >> 2;

    const int seq_len = seq_lens[s];
    const int ctx = seq_len - QLEN;
    const int qa0 = ctx + qt*64 + w*16 + g;
    const int qa1 = qa0 + 8;

    const u32 smb = smem_u32(smem);
    const int* btbase = block_tables + s*MAXBLOCKS + sp*64;

    // prologue: prefetch stages 0 and 1 into buffers 0,1
    issue_stage(smb,        btbase,     hkv, tid); CPA_COMMIT();
    issue_stage(smb + SBUF, btbase + 2, hkv, tid); CPA_COMMIT();

    // ---- Q fragments (hi/lo) in registers ----
    u32 qh[8][4], ql[8][4];
    {
        const float* q0 = query + ((size_t)(s*QLEN + qt*64 + w*16 + g)*NQH + h)*HDIM;
        const float* q8 = q0 + (size_t)8*NQH*HDIM;
        #pragma unroll
        for (int ks = 0; ks < 8; ks++){
            int d0 = ks*16 + 2*qq;
            float2 x0 = *reinterpret_cast<const float2*>(q0 + d0);
            float2 x1 = *reinterpret_cast<const float2*>(q8 + d0);
            float2 x2 = *reinterpret_cast<const float2*>(q0 + d0 + 8);
            float2 x3 = *reinterpret_cast<const float2*>(q8 + d0 + 8);
            bsplit(x0.x*SCALE_F, x0.y*SCALE_F, qh[ks][0], ql[ks][0]);
            bsplit(x1.x*SCALE_F, x1.y*SCALE_F, qh[ks][1], ql[ks][1]);
            bsplit(x2.x*SCALE_F, x2.y*SCALE_F, qh[ks][2], ql[ks][2]);
            bsplit(x3.x*SCALE_F, x3.y*SCALE_F, qh[ks][3], ql[ks][3]);
        }
    }

    float dacc[16][4];
    #pragma unroll
    for (int i = 0; i < 16; i++){ dacc[i][0]=0.f; dacc[i][1]=0.f; dacc[i][2]=0.f; dacc[i][3]=0.f; }
    float m0 = -1e30f, m1 = -1e30f;

    int bufi = 0;                                // st % 3
    #pragma unroll 1
    for (int st = 0; st < 32; st++){
        // wait for stage st's staging group, then one barrier for visibility
        if (st < 31) { CPA_WAIT(1); } else { CPA_WAIT(0); }
        __syncthreads();

        // issue prefetch of stage st+2 (overlaps entire stage compute)
        if (st + 2 < 32){
            int nb = bufi + 2; if (nb >= 3) nb -= 3;
            issue_stage(smb + nb*SBUF, btbase + (st+2)*2, hkv, tid);
            CPA_COMMIT();
        }

        const char* bufc = smem + bufi*SBUF;
        const int lb = sp*1024 + st*32;

        // ---- QK: S[16 x 32] per warp, 3-pass bf16, 1 LDS.128 per tile ----
        float sacc[4][4];
        #pragma unroll
        for (int i = 0; i < 4; i++){ sacc[i][0]=0.f; sacc[i][1]=0.f; sacc[i][2]=0.f; sacc[i][3]=0.f; }
        #pragma unroll
        for (int ks = 0; ks < 8; ks++){
            #pragma unroll
            for (int nt = 0; nt < 4; nt++){     // nt = j*2 + ntl
                uint4 kf = *reinterpret_cast<const uint4*>(
                    bufc + KOFF + (nt >> 1)*8192 + (((nt & 1)*8 + ks)*32 + lane)*16);
                mma16816(sacc[nt], qh[ks], kf.x, kf.y);
                mma16816(sacc[nt], ql[ks], kf.x, kf.y);
                mma16816(sacc[nt], qh[ks], kf.z, kf.w);
            }
        }

        // ---- softcap via odd poly of tanh + causal + p = exp(scv-30) ----
        #pragma unroll
        for (int nt = 0; nt < 4; nt++){
            #pragma unroll
            for (int e = 0; e < 4; e++){
                int lg  = lb + nt*8 + qq*2 + (e & 1);
                int row = (e < 2) ? qa0 : qa1;
                float sv = sacc[nt][e];
                sv = fminf(fmaxf(sv, -18.0f), 18.0f);
                float u = sv * sv;
                float pl = TA6;
                pl = fmaf(u, pl, TA5);
                pl = fmaf(u, pl, TA4);
                pl = fmaf(u, pl, TA3);
                pl = fmaf(u, pl, TA2);
                pl = fmaf(u, pl, TA1);
                pl = fmaf(u, pl, TA0);
                float scv = sv * pl;                 // 30*tanh(s/30)
                bool ok = (lg <= row);
                float p = ok ? __expf(scv - 30.0f) : 0.0f;
                if (ok){ if (e < 2) m0 = fmaxf(m0, scv); else m1 = fmaxf(m1, scv); }
                sacc[nt][e] = p;
            }
        }

        // ---- PV: D[16 x 128] += P * V, 3-pass bf16 ----
        #pragma unroll
        for (int ksv = 0; ksv < 2; ksv++){      // ksv = paged block j
            u32 ph[4], pl2[4];
            const float* p0 = sacc[2*ksv];
            const float* p1 = sacc[2*ksv + 1];
            bsplit(p0[0], p0[1], ph[0], pl2[0]);
            bsplit(p0[2], p0[3], ph[1], pl2[1]);
            bsplit(p1[0], p1[1], ph[2], pl2[2]);
            bsplit(p1[2], p1[3], ph[3], pl2[3]);
            #pragma unroll
            for (int ntv = 0; ntv < 16; ntv++){
                uint4 vf = *reinterpret_cast<const uint4*>(
                    bufc + VOFF + ksv*8192 + (ntv*32 + lane)*16);
                mma16816(dacc[ntv], ph, vf.x, vf.y);
                mma16816(dacc[ntv], pl2, vf.x, vf.y);
                mma16816(dacc[ntv], ph, vf.z, vf.w);
            }
        }

        // ---- segment boundary: scale by exp(30 - m), write, reset ----
        if ((st & 15) == 15){
            float a0 = m0, a1 = m1;
            #pragma unroll
            for (int o = 1; o <= 2; o <<= 1){
                a0 = fmaxf(a0, __shfl_xor_sync(0xffffffffu, a0, o));
                a1 = fmaxf(a1, __shfl_xor_sync(0xffffffffu, a1, o));
            }
            float sc0 = (a0 > -100.0f) ? __expf(30.0f - a0) : 0.0f;
            float sc1 = (a1 > -100.0f) ? __expf(30.0f - a1) : 0.0f;
            const int seg = sp*2 + (st >> 4);
            const int t0 = s*QLEN + qt*64 + w*16 + g;
            float* o0 = out + (((size_t)t0*NQH + h)*4 + seg)*HDIM;
            float* o1 = o0 + (size_t)8*NQH*4*HDIM;
            #pragma unroll
            for (int nt = 0; nt < 16; nt++){
                int dv = nt*8 + qq*2;
                *reinterpret_cast<float2*>(o0 + dv) =
                    make_float2(dacc[nt][0]*sc0, dacc[nt][1]*sc0);
                *reinterpret_cast<float2*>(o1 + dv) =
                    make_float2(dacc[nt][2]*sc1, dacc[nt][3]*sc1);
                dacc[nt][0]=0.f; dacc[nt][1]=0.f; dacc[nt][2]=0.f; dacc[nt][3]=0.f;
            }
            m0 = -1e30f; m1 = -1e30f;
        }

        bufi++; if (bufi == 3) bufi = 0;
    }
}

extern "C" void kernel_launch(void* const* d_in, const int* in_sizes, int n_in,
                              void* d_out, int out_size) {
    (void)in_sizes; (void)n_in; (void)out_size;
    const float* query        = (const float*)d_in[0];
    const float* key_cache    = (const float*)d_in[1];
    const float* value_cache  = (const float*)d_in[2];
    const int*   block_tables = (const int*)d_in[3];
    const int*   seq_lens     = (const int*)d_in[4];
    float* out = (float*)d_out;

    convert_kv_kernel<<<8192, 256>>>(key_cache, value_cache);

    cudaFuncSetAttribute(Model_3470333575380_kernel,
                         cudaFuncAttributeMaxDynamicSharedMemorySize, SMEM_BYTES);
    Model_3470333575380_kernel<<<NUM_SEQS*NQH*2*2, NTHR, SMEM_BYTES>>>(
        query, block_tables, seq_lens, out);
}